// round 13
// baseline (speedup 1.0000x reference)
#include <cuda_runtime.h>
#include <cstdint>

// Aggregator: masked mean of sampled neighbor features.
//  d_in[0] features:      [N, 128] float32
//  d_in[1] neighbor_idx:  [N, 16]  int32
//  d_in[2] neighbor_mask: [N, 16]  int32 (0/1)
//  d_out   out:           [N, 128] float32
//
// TWO nodes per warp, processed with a batched prologue: both nodes'
// idx/mask vectors load up front (they share 128B cache lines), then both
// nodes' gathers issue interleaved as independent predicated chains. This
// amortizes the exposed idx-load latency bubble (DRAM-streamed) over twice
// the gather work, which is the remaining idle fraction of the L1tex pipe.
// Lane layout unchanged from the 47us baseline: lane l owns float4 cols
// [4l,4l+4); flat fully-unrolled @P LDG.128.CG; packed f32x2 accumulation.

#define S 16
#define D 128

__device__ __forceinline__ unsigned long long addx2(unsigned long long a, unsigned long long b) {
    unsigned long long r;
    asm("add.rn.f32x2 %0, %1, %2;" : "=l"(r) : "l"(a), "l"(b));
    return r;
}

__global__ __launch_bounds__(256) void agg_kernel(
    const float* __restrict__ feat,
    const int* __restrict__ nidx,
    const int* __restrict__ mask,
    float* __restrict__ out,
    int n)
{
    int warp = (int)((blockIdx.x * (unsigned)blockDim.x + threadIdx.x) >> 5);
    int lane = threadIdx.x & 31;
    int node0 = 2 * warp;
    if (node0 >= n) return;
    bool has1 = (node0 + 1) < n;

    // ---- batched prologue: idx+mask for BOTH nodes (32 ints each) ----
    // nodes 2w,2w+1 are contiguous: their idx (and mask) blocks tile whole
    // 128B lines -> half the idx/mask wavefronts of one-node-per-warp.
    const int4* mp = reinterpret_cast<const int4*>(mask + (size_t)node0 * S);
    const int4* ip = reinterpret_cast<const int4*>(nidx + (size_t)node0 * S);

    unsigned nz0 = 0, nz1 = 0;
#pragma unroll
    for (int q = 0; q < 4; q++) {
        int4 m = __ldg(mp + q);
        nz0 |= (unsigned)(m.x != 0) << (4 * q + 0);
        nz0 |= (unsigned)(m.y != 0) << (4 * q + 1);
        nz0 |= (unsigned)(m.z != 0) << (4 * q + 2);
        nz0 |= (unsigned)(m.w != 0) << (4 * q + 3);
    }
    if (has1) {
#pragma unroll
        for (int q = 0; q < 4; q++) {
            int4 m = __ldg(mp + 4 + q);
            nz1 |= (unsigned)(m.x != 0) << (4 * q + 0);
            nz1 |= (unsigned)(m.y != 0) << (4 * q + 1);
            nz1 |= (unsigned)(m.z != 0) << (4 * q + 2);
            nz1 |= (unsigned)(m.w != 0) << (4 * q + 3);
        }
    }
    int cnt0 = __popc(nz0);
    int cnt1 = __popc(nz1);

    int idx0[S], idx1[S];
#pragma unroll
    for (int q = 0; q < 4; q++) {
        int4 v = __ldg(ip + q);
        idx0[4 * q + 0] = v.x; idx0[4 * q + 1] = v.y;
        idx0[4 * q + 2] = v.z; idx0[4 * q + 3] = v.w;
    }
#pragma unroll
    for (int q = 0; q < 4; q++) {
        int4 v = has1 ? __ldg(ip + 4 + q) : make_int4(0, 0, 0, 0);
        idx1[4 * q + 0] = v.x; idx1[4 * q + 1] = v.y;
        idx1[4 * q + 2] = v.z; idx1[4 * q + 3] = v.w;
    }

    // ---- interleaved predicated gathers: two independent chains ----
    unsigned long long aLo0 = 0ull, aHi0 = 0ull;   // bitwise 0 == (0.f,0.f)
    unsigned long long aLo1 = 0ull, aHi1 = 0ull;
#pragma unroll
    for (int j = 0; j < S; j++) {
        if ((nz0 >> j) & 1u) {
            const float4* row =
                reinterpret_cast<const float4*>(feat + (size_t)idx0[j] * D) + lane;
            float4 v = __ldcg(row);
            unsigned long long lo, hi;
            asm("mov.b64 %0, {%1, %2};" : "=l"(lo) : "f"(v.x), "f"(v.y));
            asm("mov.b64 %0, {%1, %2};" : "=l"(hi) : "f"(v.z), "f"(v.w));
            aLo0 = addx2(aLo0, lo);
            aHi0 = addx2(aHi0, hi);
        }
        if ((nz1 >> j) & 1u) {
            const float4* row =
                reinterpret_cast<const float4*>(feat + (size_t)idx1[j] * D) + lane;
            float4 v = __ldcg(row);
            unsigned long long lo, hi;
            asm("mov.b64 %0, {%1, %2};" : "=l"(lo) : "f"(v.x), "f"(v.y));
            asm("mov.b64 %0, {%1, %2};" : "=l"(hi) : "f"(v.z), "f"(v.w));
            aLo1 = addx2(aLo1, lo);
            aHi1 = addx2(aHi1, hi);
        }
    }

    // ---- scale + store both nodes ----
    {
        float inv = 1.0f / (float)(cnt0 > 0 ? cnt0 : 1);
        float x, y, z, w;
        asm("mov.b64 {%0, %1}, %2;" : "=f"(x), "=f"(y) : "l"(aLo0));
        asm("mov.b64 {%0, %1}, %2;" : "=f"(z), "=f"(w) : "l"(aHi0));
        float4 r = make_float4(x * inv, y * inv, z * inv, w * inv);
        __stcg(reinterpret_cast<float4*>(out) + (size_t)node0 * (D / 4) + lane, r);
    }
    if (has1) {
        float inv = 1.0f / (float)(cnt1 > 0 ? cnt1 : 1);
        float x, y, z, w;
        asm("mov.b64 {%0, %1}, %2;" : "=f"(x), "=f"(y) : "l"(aLo1));
        asm("mov.b64 {%0, %1}, %2;" : "=f"(z), "=f"(w) : "l"(aHi1));
        float4 r = make_float4(x * inv, y * inv, z * inv, w * inv);
        __stcg(reinterpret_cast<float4*>(out) + (size_t)(node0 + 1) * (D / 4) + lane, r);
    }
}

extern "C" void kernel_launch(void* const* d_in, const int* in_sizes, int n_in,
                              void* d_out, int out_size)
{
    const float* feat = (const float*)d_in[0];
    const int*   nidx = (const int*)d_in[1];
    const int*   mask = (const int*)d_in[2];
    float*       out  = (float*)d_out;

    int n = in_sizes[1] / S;                    // 100000 nodes
    int pairs = (n + 1) / 2;                    // 2 nodes per warp
    int warps_per_block = 256 / 32;             // 8
    int blocks = (pairs + warps_per_block - 1) / warps_per_block;
    agg_kernel<<<blocks, 256>>>(feat, nidx, mask, out, n);
}

// round 14
// speedup vs baseline: 1.0564x; 1.0564x over previous
#include <cuda_runtime.h>
#include <cstdint>

// Aggregator: masked mean of sampled neighbor features.
//  d_in[0] features:      [N, 128] float32
//  d_in[1] neighbor_idx:  [N, 16]  int32
//  d_in[2] neighbor_mask: [N, 16]  int32 (0/1)
//  d_out   out:           [N, 128] float32
//
// Persistent chunked warps + cp.async (LDGSTS) double-ahead prefetch of
// idx/mask blocks into smem. This hides the exposed index-load latency
// phase WITHOUT the register cost that sank the R13 attempt: LDGSTS has no
// destination registers, and gather indices are consumed straight from
// smem broadcasts. Gather core unchanged from the 47us baseline: flat
// fully-unrolled @P LDG.128.CG, packed f32x2 accumulation, STG.CG output.

#define S 16
#define D 128
#define WPB 8          // warps per block (256 threads)
#define STAGES 3       // smem stages; prefetch depth 2
#define NBLOCKS 888    // ~6 blocks/SM on 148 SMs, persistent-ish

__device__ __forceinline__ unsigned long long addx2(unsigned long long a, unsigned long long b) {
    unsigned long long r;
    asm("add.rn.f32x2 %0, %1, %2;" : "=l"(r) : "l"(a), "l"(b));
    return r;
}

__device__ __forceinline__ unsigned smem_u32(const void* p) {
    return (unsigned)__cvta_generic_to_shared(p);
}

__global__ __launch_bounds__(256) void agg_kernel(
    const float* __restrict__ feat,
    const int* __restrict__ nidx,
    const int* __restrict__ mask,
    float* __restrict__ out,
    int n)
{
    // [stage][warp][0..15]=idx, [16..31]=mask
    __shared__ int sbuf[STAGES][WPB][32];

    int wid  = threadIdx.x >> 5;
    int lane = threadIdx.x & 31;
    int gwarp = blockIdx.x * WPB + wid;
    int total_warps = NBLOCKS * WPB;

    int chunk = (n + total_warps - 1) / total_warps;   // nodes per warp
    int start = gwarp * chunk;
    int end   = min(start + chunk, n);
    if (start >= end) return;

    // ---- prefetch helper: lanes 0-7 move 64B idx + 64B mask for `node` ----
    auto issue = [&](int stage, int node) {
        if (lane < 8) {
            int  q    = lane & 3;
            bool is_m = lane >= 4;
            const int* src = (is_m ? mask : nidx) + (size_t)node * S + q * 4;
            unsigned dst = smem_u32(&sbuf[stage][wid][(is_m ? 16 : 0) + q * 4]);
            asm volatile("cp.async.ca.shared.global [%0], [%1], 16;"
                         :: "r"(dst), "l"(src));
        }
        asm volatile("cp.async.commit_group;");        // all lanes: keep group count uniform
    };

    // ---- prologue: fill 2 stages (empty groups if past end) ----
    if (start + 0 < end) issue(0, start + 0); else asm volatile("cp.async.commit_group;");
    if (start + 1 < end) issue(1, start + 1); else asm volatile("cp.async.commit_group;");

    for (int t = start; t < end; t++) {
        int s = (t - start) % STAGES;

        // prefetch node t+2 into stage (s+2)%STAGES; always commit one group
        int tf = t + 2;
        if (tf < end) issue((s + 2) % STAGES, tf);
        else          asm volatile("cp.async.commit_group;");

        // wait until node t's group has landed (2 groups may stay in flight)
        asm volatile("cp.async.wait_group 2;");
        __syncwarp();

        const int* p = &sbuf[s][wid][0];

        // ---- mask bits + count from smem (broadcast LDS) ----
        unsigned nz = 0;
#pragma unroll
        for (int j = 0; j < S; j++)
            nz |= (unsigned)(p[16 + j] != 0) << j;
        int cnt = __popc(nz);

        // ---- flat predicated gathers: @P LDG.128.CG, packed f32x2 ----
        unsigned long long aLo = 0ull, aHi = 0ull;     // bitwise 0 == (0.f,0.f)
#pragma unroll
        for (int j = 0; j < S; j++) {
            if ((nz >> j) & 1u) {
                const float4* row =
                    reinterpret_cast<const float4*>(feat + (size_t)p[j] * D) + lane;
                float4 v = __ldcg(row);
                unsigned long long lo, hi;
                asm("mov.b64 %0, {%1, %2};" : "=l"(lo) : "f"(v.x), "f"(v.y));
                asm("mov.b64 %0, {%1, %2};" : "=l"(hi) : "f"(v.z), "f"(v.w));
                aLo = addx2(aLo, lo);
                aHi = addx2(aHi, hi);
            }
        }

        // ---- scale + store ----
        float inv = 1.0f / (float)(cnt > 0 ? cnt : 1);
        float x, y, z, w;
        asm("mov.b64 {%0, %1}, %2;" : "=f"(x), "=f"(y) : "l"(aLo));
        asm("mov.b64 {%0, %1}, %2;" : "=f"(z), "=f"(w) : "l"(aHi));
        float4 r = make_float4(x * inv, y * inv, z * inv, w * inv);
        __stcg(reinterpret_cast<float4*>(out) + (size_t)t * (D / 4) + lane, r);

        __syncwarp();   // all lanes done reading stage s before it is refilled
    }
}

extern "C" void kernel_launch(void* const* d_in, const int* in_sizes, int n_in,
                              void* d_out, int out_size)
{
    const float* feat = (const float*)d_in[0];
    const int*   nidx = (const int*)d_in[1];
    const int*   mask = (const int*)d_in[2];
    float*       out  = (float*)d_out;

    int n = in_sizes[1] / S;              // 100000 nodes
    agg_kernel<<<NBLOCKS, 256>>>(feat, nidx, mask, out, n);
}